// round 10
// baseline (speedup 1.0000x reference)
#include <cuda_runtime.h>

// reblurWithKernel: spatially-varying 33x33 blur, per-4x4-block kernels.
// out[c,h,w] = sum_{u,v} in[clamp(h+u-16),clamp(w+v-16)] * K[u*33+v, h/4, w/4]
//
// R9: packed fp32 math via fma.rn.f32x2 (FFMA2), acc paired across output
// rows oi: acc01[j] = (out[oi0][j], out[oi1][j]). Multiplier is broadcast
// (k,k); data operand is the interleaved pair (row[R][x], row[R+1][x]) read
// natively from smem. Two interleaved patch copies (even/odd row pairing)
// cover both u parities. Pair-rows stored split A-chunks (pair idx 0,1 mod 4)
// / B-chunks (2,3 mod 4) so warp LDS.128s are lane-dense.
// 512 threads = 16 warps, warp g handles u = g, g+16 for ALL 3 channels
// (kr loaded once per u per CTA -> 3x less kernel LDG than per-channel warps;
// 128-reg budget -> no spills). Row u=32: warps 0-7 take 4 taps, warp 8 tap 32.
// Group-combine via smem [g][k][lane] layout, warps 0-2 reduce one channel each.

#define KW     33
#define BLK    4
#define PAD    16
#define HH     512
#define WW     512
#define HB     128
#define WBNUM  128
#define KSTRIDE (HB*WBNUM)        // 16384 elements between taps
#define TWB    32                 // wb blocks per CTA
#define PCOLS  160                // patch cols = pair index range
#define ROWD   164                // 64-bit words per pair-row (A at 0, B at 82)
#define BOFF_B 656u               // byte offset of B region (82*8)
#define PAIRROWS 35               // 18 even-paired + 17 odd-paired
#define NTH    512
#define SMEM_BYTES (3 * PAIRROWS * ROWD * 8)   // 137760 B

typedef unsigned long long ull;

__device__ __forceinline__ ull pack2(float lo, float hi) {
    ull r;
    asm("mov.b64 %0, {%1, %2};"
        : "=l"(r) : "r"(__float_as_uint(lo)), "r"(__float_as_uint(hi)));
    return r;
}
__device__ __forceinline__ void unpack2(ull v, float& lo, float& hi) {
    unsigned int a, b;
    asm("mov.b64 {%0, %1}, %2;" : "=r"(a), "=r"(b) : "l"(v));
    lo = __uint_as_float(a); hi = __uint_as_float(b);
}
__device__ __forceinline__ ull fma2(ull a, ull b, ull c) {
    ull d;
    asm("fma.rn.f32x2 %0, %1, %2, %3;" : "=l"(d) : "l"(a), "l"(b), "l"(c));
    return d;
}
__device__ __forceinline__ ull add2(ull a, ull b) {
    ull d;
    asm("add.rn.f32x2 %0, %1, %2;" : "=l"(d) : "l"(a), "l"(b));
    return d;
}
__device__ __forceinline__ void lds2(unsigned int addr, ull& a, ull& b) {
    asm volatile("ld.shared.v2.u64 {%0, %1}, [%2];"
                 : "=l"(a), "=l"(b) : "r"(addr));
}

// 4 consecutive taps at base v. Window doubles cover t = 0..6 rel to base:
// a0=t0 a1=t1 b0=t2 b1=t3 a2=t4 a3=t5 b2=t6
__device__ __forceinline__ void quad_taps(const float* kq,
    ull a0, ull a1, ull b0, ull b1, ull a2, ull a3, ull b2, ull* acc)
{
    ull KK;
    KK = pack2(kq[0], kq[0]);
    acc[0]=fma2(KK,a0,acc[0]); acc[1]=fma2(KK,a1,acc[1]);
    acc[2]=fma2(KK,b0,acc[2]); acc[3]=fma2(KK,b1,acc[3]);
    KK = pack2(kq[1], kq[1]);
    acc[0]=fma2(KK,a1,acc[0]); acc[1]=fma2(KK,b0,acc[1]);
    acc[2]=fma2(KK,b1,acc[2]); acc[3]=fma2(KK,a2,acc[3]);
    KK = pack2(kq[2], kq[2]);
    acc[0]=fma2(KK,b0,acc[0]); acc[1]=fma2(KK,b1,acc[1]);
    acc[2]=fma2(KK,a2,acc[2]); acc[3]=fma2(KK,a3,acc[3]);
    KK = pack2(kq[3], kq[3]);
    acc[0]=fma2(KK,b1,acc[0]); acc[1]=fma2(KK,a2,acc[1]);
    acc[2]=fma2(KK,a3,acc[2]); acc[3]=fma2(KK,b2,acc[3]);
}

__device__ __forceinline__ unsigned int pair_row_base(unsigned int sbase,
                                                      int c, int R)
{
    const int pr = (R & 1) ? (18 + (R >> 1)) : (R >> 1);
    return sbase + (unsigned)((c * PAIRROWS + pr) * ROWD) * 8u;
}

// Full tap row u over paired rows (R, R+1): v = 0..32, sliding chunk window.
__device__ __forceinline__ void do_group(unsigned int sbase, int c, int R,
                                         int lane, const float* kr, ull* acc)
{
    const unsigned int rb    = pair_row_base(sbase, c, R);
    const unsigned int aAddr = rb + (unsigned)lane * 16u;
    const unsigned int bAddr = aAddr + BOFF_B;

    ull a0,a1,b0,b1,a2,a3,b2,b3;
    lds2(aAddr,      a0, a1);
    lds2(bAddr,      b0, b1);
    lds2(aAddr + 16, a2, a3);
    lds2(bAddr + 16, b2, b3);
#pragma unroll
    for (int s = 0; s < 8; s++) {
        quad_taps(kr + 4 * s, a0, a1, b0, b1, a2, a3, b2, acc);
        a0 = a2; a1 = a3; b0 = b2; b1 = b3;
        if (s < 7) {
            lds2(aAddr + (unsigned)(s + 2) * 16u, a2, a3);
            lds2(bAddr + (unsigned)(s + 2) * 16u, b2, b3);
        }
    }
    // v = 32: t = 32..35 = chunk 8 (rotated into a0,a1,b0,b1)
    ull KK = pack2(kr[32], kr[32]);
    acc[0]=fma2(KK,a0,acc[0]); acc[1]=fma2(KK,a1,acc[1]);
    acc[2]=fma2(KK,b0,acc[2]); acc[3]=fma2(KK,b1,acc[3]);
}

// Tap row u=32 slice: 4 taps v = 4g..4g+3 on even pair rows (R = 32 or 34).
__device__ __forceinline__ void partial32(unsigned int sbase, int c, int R,
                                          int lane, int g, const float* kq,
                                          ull* acc)
{
    const unsigned int rb    = pair_row_base(sbase, c, R);
    const unsigned int aAddr = rb + (unsigned)(lane + g) * 16u;
    const unsigned int bAddr = aAddr + BOFF_B;

    ull a0,a1,b0,b1,a2,a3,b2,b3;
    lds2(aAddr,      a0, a1);
    lds2(bAddr,      b0, b1);
    lds2(aAddr + 16, a2, a3);
    lds2(bAddr + 16, b2, b3);
    (void)b3;
    quad_taps(kq, a0, a1, b0, b1, a2, a3, b2, acc);
}

// Tap row u=32, tap v=32 only (warp 8).
__device__ __forceinline__ void tap32(unsigned int sbase, int c, int R,
                                      int lane, float k32, ull* acc)
{
    const unsigned int rb    = pair_row_base(sbase, c, R);
    const unsigned int aAddr = rb + (unsigned)(lane + 8) * 16u;  // cols 32..35
    const unsigned int bAddr = aAddr + BOFF_B;
    ull a0,a1,b0,b1;
    lds2(aAddr, a0, a1);
    lds2(bAddr, b0, b1);
    ull KK = pack2(k32, k32);
    acc[0]=fma2(KK,a0,acc[0]); acc[1]=fma2(KK,a1,acc[1]);
    acc[2]=fma2(KK,b0,acc[2]); acc[3]=fma2(KK,b1,acc[3]);
}

__global__ __launch_bounds__(NTH, 1)
void reblur_kernel(const float* __restrict__ img,
                   const float* __restrict__ ker,
                   float* __restrict__ out)
{
    extern __shared__ __align__(16) char smem[];
    unsigned int sbase;
    asm("{ .reg .u64 t; cvta.to.shared.u64 t, %1; cvt.u32.u64 %0, t; }"
        : "=r"(sbase) : "l"(smem));

    const int tid = threadIdx.x;
    const int WB0 = blockIdx.x * TWB;
    const int HB0 = blockIdx.y;

    // ---- build interleaved patch copies (edge-clamped), 3 channels ----
    const int row0 = HB0 * BLK - PAD;
    const int col0 = WB0 * BLK - PAD;
    for (int idx = tid; idx < 3 * PAIRROWS * PCOLS; idx += NTH) {
        int c   = idx / (PAIRROWS * PCOLS);
        int rem = idx - c * (PAIRROWS * PCOLS);
        int pr  = rem / PCOLS;
        int x   = rem - pr * PCOLS;
        int R0  = (pr < 18) ? (2 * pr) : (2 * (pr - 18) + 1);
        int ir0 = min(max(row0 + R0, 0), HH - 1);
        int ir1 = min(max(row0 + R0 + 1, 0), HH - 1);
        int ic  = min(max(col0 + x, 0), WW - 1);
        float va = img[c * (HH * WW) + ir0 * WW + ic];
        float vb = img[c * (HH * WW) + ir1 * WW + ic];
        int m = x >> 2, s4 = x & 3;
        int didx = (s4 < 2) ? (2 * m + s4) : (82 + 2 * m + (s4 - 2));
        *reinterpret_cast<ull*>(smem + ((c * PAIRROWS + pr) * ROWD + didx) * 8)
            = pack2(va, vb);
    }
    __syncthreads();

    // ---- work mapping: 16 warps = 16 u-groups; each warp does 3 channels ----
    const int g    = tid >> 5;   // 0..15, u = g + 16m
    const int lane = tid & 31;   // wb block within tile

    ull acc[3][8];               // [c][0..3]=rows(oi0,oi1), [4..7]=rows(oi2,oi3)
#pragma unroll
    for (int c = 0; c < 3; c++)
#pragma unroll
        for (int j = 0; j < 8; j++)
            acc[c][j] = 0ull;

    const float* kbase = ker + HB0 * WBNUM + (WB0 + lane);

#pragma unroll 1
    for (int m = 0; m < 2; m++) {
        const int u = g + 16 * m;
        float kr[KW];            // one kernel row; 1 coalesced wavefront/LDG
        const float* kp = kbase + (u * KW) * KSTRIDE;
#pragma unroll
        for (int v = 0; v < KW; v++)
            kr[v] = __ldg(kp + v * KSTRIDE);
#pragma unroll
        for (int c = 0; c < 3; c++) {
            do_group(sbase, c, u,     lane, kr, &acc[c][0]);
            do_group(sbase, c, u + 2, lane, kr, &acc[c][4]);
        }
    }

    // ---- tap row u=32 ----
    if (g < 8) {
        float kq[4];
        const float* kp = kbase + (32 * KW + 4 * g) * KSTRIDE;
#pragma unroll
        for (int i = 0; i < 4; i++)
            kq[i] = __ldg(kp + i * KSTRIDE);
#pragma unroll
        for (int c = 0; c < 3; c++) {
            partial32(sbase, c, 32, lane, g, kq, &acc[c][0]);
            partial32(sbase, c, 34, lane, g, kq, &acc[c][4]);
        }
    } else if (g == 8) {
        float k32 = __ldg(kbase + (32 * KW + 32) * KSTRIDE);
#pragma unroll
        for (int c = 0; c < 3; c++) {
            tap32(sbase, c, 32, lane, k32, &acc[c][0]);
            tap32(sbase, c, 34, lane, k32, &acc[c][4]);
        }
    }

    // ---- combine 16 u-groups: smem layout red[g][k=0..23][lane] ----
    __syncthreads();               // everyone done reading the patch
    ull* red = reinterpret_cast<ull*>(smem);
#pragma unroll
    for (int c = 0; c < 3; c++)
#pragma unroll
        for (int j = 0; j < 8; j++)
            red[(g * 24 + c * 8 + j) * 32 + lane] = acc[c][j];
    __syncthreads();

    if (g < 3) {                   // warp g reduces + stores channel g
        const int c = g;
        ull s[8];
#pragma unroll
        for (int j = 0; j < 8; j++) s[j] = 0ull;
#pragma unroll
        for (int p = 0; p < 16; p++)
#pragma unroll
            for (int j = 0; j < 8; j++)
                s[j] = add2(s[j], red[(p * 24 + c * 8 + j) * 32 + lane]);

        float o0[4], o1[4], o2[4], o3[4];
#pragma unroll
        for (int j = 0; j < 4; j++) {
            unpack2(s[j],     o0[j], o1[j]);
            unpack2(s[4 + j], o2[j], o3[j]);
        }
        float* ob = out + c * (HH * WW) + (HB0 * BLK) * WW + (WB0 + lane) * BLK;
        *reinterpret_cast<float4*>(ob + 0 * WW) = make_float4(o0[0], o0[1], o0[2], o0[3]);
        *reinterpret_cast<float4*>(ob + 1 * WW) = make_float4(o1[0], o1[1], o1[2], o1[3]);
        *reinterpret_cast<float4*>(ob + 2 * WW) = make_float4(o2[0], o2[1], o2[2], o2[3]);
        *reinterpret_cast<float4*>(ob + 3 * WW) = make_float4(o3[0], o3[1], o3[2], o3[3]);
    }
}

extern "C" void kernel_launch(void* const* d_in, const int* in_sizes, int n_in,
                              void* d_out, int out_size)
{
    const float* img = (const float*)d_in[0];  // (1,3,512,512) fp32
    const float* ker = (const float*)d_in[1];  // (1,1089,128,128) fp32
    float* out = (float*)d_out;                // (1,3,512,512) fp32
    (void)in_sizes; (void)n_in; (void)out_size;

    cudaFuncSetAttribute(reblur_kernel,
                         cudaFuncAttributeMaxDynamicSharedMemorySize, SMEM_BYTES);

    dim3 grid(WBNUM / TWB, HB);  // (4, 128) = 512 CTAs
    reblur_kernel<<<grid, NTH, SMEM_BYTES>>>(img, ker, out);
}